// round 4
// baseline (speedup 1.0000x reference)
#include <cuda_runtime.h>
#include <cstdint>

// ---------------------------------------------------------------------------
// Problem constants (shapes fixed by setup_inputs: N=200000, D=128, P=10)
// ---------------------------------------------------------------------------
#define DDIM      128
#define NMAXPAD   200704          // >= ceil(200000/256)*256
#define NBMAX     784             // NMAXPAD/256

#define CHUNKS    2048            // L1 chunks per hull
#define CAP       104             // per-chunk candidate cap (ceil(200000/2048)=98)
#define L2GROUPS  32
#define CHPERGRP  (CHUNKS / L2GROUPS)      // 64
#define L2STRIDE  (CHPERGRP * CAP)         // 6656
#define MAXIT     48

// ---------------------------------------------------------------------------
// Static device scratch (no allocations allowed)
// ---------------------------------------------------------------------------
__device__ unsigned g_keysA[NMAXPAD];
__device__ unsigned g_keysB[NMAXPAD];
__device__ unsigned g_hist  [256 * NBMAX];
__device__ unsigned g_prefix[256 * NBMAX];
__device__ unsigned g_digitTotal[256];
__device__ unsigned g_digitBase[256];
__device__ double   g_xs[NMAXPAD + 2];       // 1-based sorted values (double)

// hull scratch
__device__ int g_candLo[CHUNKS * CAP];
__device__ int g_candUp[CHUNKS * CAP];
__device__ int g_candCntLo[CHUNKS];
__device__ int g_candCntUp[CHUNKS];
__device__ int g_l2Lo[L2GROUPS * L2STRIDE];
__device__ int g_l2Up[L2GROUPS * L2STRIDE];
__device__ int g_l2CntLo[L2GROUPS];
__device__ int g_l2CntUp[L2GROUPS];
__device__ int g_hullLo[NMAXPAD + 2];
__device__ int g_hullUp[NMAXPAD + 2];
__device__ int g_gcm[NMAXPAD + 2];
__device__ int g_lcm[NMAXPAD + 2];
__device__ double g_segCLo[NMAXPAD + 2];
__device__ double g_segCUp[NMAXPAD + 2];

// dip iteration state
__device__ int    g_low, g_high, g_done;
__device__ int    g_ig, g_ih, g_lgcm, g_llcm;
__device__ double g_dip;
__device__ unsigned long long g_scanmax;

// ---------------------------------------------------------------------------
// 1) Projection: x_proj[i] = dot(X[i,:], p)  (warp per row), write sortable key
// ---------------------------------------------------------------------------
__global__ void proj_kernel(const float* __restrict__ X,
                            const float* __restrict__ P,
                            const int* __restrict__ idx,
                            int N, int NPAD)
{
    int gtid   = blockIdx.x * blockDim.x + threadIdx.x;
    int warpId = gtid >> 5;
    int lane   = threadIdx.x & 31;

    const float4* p4 = (const float4*)(P + (size_t)(*idx) * DDIM);
    float4 pv = p4[lane];

    if (warpId < N) {
        const float4* x4 = (const float4*)(X + (size_t)warpId * DDIM);
        float4 xv = x4[lane];
        float s = xv.x * pv.x + xv.y * pv.y + xv.z * pv.z + xv.w * pv.w;
        #pragma unroll
        for (int off = 16; off; off >>= 1)
            s += __shfl_xor_sync(0xffffffffu, s, off);
        if (lane == 0) {
            unsigned b = __float_as_uint(s);
            g_keysA[warpId] = (b & 0x80000000u) ? ~b : (b | 0x80000000u);
        }
    }
    if (gtid < NPAD - N) g_keysA[N + gtid] = 0xFFFFFFFFu;
}

// ---------------------------------------------------------------------------
// 2) Radix sort: 4 passes x 8 bits
// ---------------------------------------------------------------------------
__global__ void hist_kernel(int srcIsA, int shift, int NB)
{
    const unsigned* in = srcIsA ? g_keysA : g_keysB;
    __shared__ unsigned sh[256];
    sh[threadIdx.x] = 0;
    __syncthreads();
    unsigned key = in[blockIdx.x * 256 + threadIdx.x];
    atomicAdd(&sh[(key >> shift) & 255u], 1u);
    __syncthreads();
    g_hist[threadIdx.x * NB + blockIdx.x] = sh[threadIdx.x];
}

__global__ void scan_digit_kernel(int NB)
{
    int d = blockIdx.x;
    int t = threadIdx.x;
    __shared__ unsigned sh[256];
    __shared__ unsigned s_tot;
    unsigned carry = 0;
    for (int base = 0; base < NB; base += 256) {
        int i = base + t;
        unsigned v = (i < NB) ? g_hist[d * NB + i] : 0u;
        sh[t] = v;
        __syncthreads();
        unsigned x = v;
        #pragma unroll
        for (int off = 1; off < 256; off <<= 1) {
            unsigned y = (t >= off) ? sh[t - off] : 0u;
            __syncthreads();
            if (t >= off) x += y;
            sh[t] = x;
            __syncthreads();
        }
        if (i < NB) g_prefix[d * NB + i] = carry + x - v;
        if (t == 255) s_tot = x;
        __syncthreads();
        carry += s_tot;
        __syncthreads();
    }
    if (t == 0) g_digitTotal[d] = carry;
}

__global__ void scan_base_kernel()
{
    int t = threadIdx.x;
    __shared__ unsigned sh[256];
    unsigned v = g_digitTotal[t];
    sh[t] = v;
    __syncthreads();
    unsigned x = v;
    #pragma unroll
    for (int off = 1; off < 256; off <<= 1) {
        unsigned y = (t >= off) ? sh[t - off] : 0u;
        __syncthreads();
        if (t >= off) x += y;
        sh[t] = x;
        __syncthreads();
    }
    g_digitBase[t] = x - v;
}

__global__ void scatter_kernel(int srcIsA, int shift, int NB)
{
    const unsigned* in  = srcIsA ? g_keysA : g_keysB;
    unsigned*       out = srcIsA ? g_keysB : g_keysA;
    __shared__ unsigned warpHist[8][256];
    int t = threadIdx.x, w = t >> 5, lane = t & 31;
    for (int i = t; i < 8 * 256; i += 256) ((unsigned*)warpHist)[i] = 0u;
    __syncthreads();

    unsigned key = in[blockIdx.x * 256 + t];
    unsigned d   = (key >> shift) & 255u;
    unsigned peers = __match_any_sync(0xffffffffu, d);
    unsigned rank  = __popc(peers & ((1u << lane) - 1u));
    int leader = __ffs(peers) - 1;
    if (lane == leader) warpHist[w][d] = __popc(peers);
    __syncthreads();

    unsigned base = 0;
    for (int w2 = 0; w2 < w; ++w2) base += warpHist[w2][d];
    unsigned pos = g_digitBase[d] + g_prefix[d * NB + blockIdx.x] + base + rank;
    out[pos] = key;
}

// ---------------------------------------------------------------------------
// 3) Finalize: inverse key transform, store sorted doubles 1-based in g_xs
// ---------------------------------------------------------------------------
__global__ void finalize_kernel(int N)
{
    int i = blockIdx.x * blockDim.x + threadIdx.x;
    if (i == 0) g_xs[0] = 0.0;
    if (i < N) {
        unsigned k = g_keysA[i];
        unsigned b = (k & 0x80000000u) ? (k ^ 0x80000000u) : ~k;
        g_xs[i + 1] = (double)__uint_as_float(b);
    }
}

__global__ void dip_init_kernel(float* out, int N)
{
    g_low = 1; g_high = N; g_dip = 1.0;
    g_done = (N < 4 || g_xs[1] == g_xs[N]) ? 1 : 0;
    out[0] = (float)(1.0 / (2.0 * (double)(N > 1 ? N : 1)));
}

// ---------------------------------------------------------------------------
// Graham push with the exact reference pop predicate:
// pop top t (below b) for new point c when NOT [(x_c-x_t)(t-b) < (x_t-x_b)(c-t)].
// Works for both lower hull (ascending idx) and upper hull (descending idx).
// ---------------------------------------------------------------------------
__device__ __forceinline__ void graham_push(int* st, int& sp, int idx, double x)
{
    while (sp >= 2) {
        int t = st[sp - 1], b = st[sp - 2];
        double xt = g_xs[t], xb = g_xs[b];
        if ((x - xt) * (double)(t - b) < (xt - xb) * (double)(idx - t)) break;
        --sp;
    }
    st[sp++] = idx;
}

// ---------------------------------------------------------------------------
// kA: level-1 chunk hulls. 2048 chunks per hull; blocks 0..7 lower, 8..15 upper.
// Lower hull domain: indices [1..high] ascending. Upper: [low..N] descending.
// ---------------------------------------------------------------------------
__global__ void hull_l1_kernel(int N)
{
    if (g_done) return;
    int gt = blockIdx.x * blockDim.x + threadIdx.x;
    int upper = (gt >= CHUNKS);
    int c = upper ? gt - CHUNKS : gt;
    if (c >= CHUNKS) return;

    int low = g_low, high = g_high;
    int M = upper ? (N - low + 1) : high;
    int cs = (M + CHUNKS - 1) / CHUNKS;
    long p0 = (long)c * cs;
    long p1 = p0 + cs; if (p1 > M) p1 = M;

    int* st = (upper ? g_candUp : g_candLo) + (size_t)c * CAP;
    int sp = 0;
    for (long p = p0; p < p1; ++p) {
        int idx = upper ? (N - (int)p) : (1 + (int)p);
        graham_push(st, sp, idx, g_xs[idx]);
    }
    (upper ? g_candCntUp : g_candCntLo)[c] = sp;
}

// ---------------------------------------------------------------------------
// kB: merge chunk hulls (L2: 32 groups/hull, L3: sequential), build gcm/lcm
// chains in reference layout, run the zigzag, precompute per-segment C.
// ---------------------------------------------------------------------------
__global__ void __launch_bounds__(1024, 1) merge_kernel(int N)
{
    if (g_done) return;
    int tid = threadIdx.x;
    __shared__ int s_mLo, s_mUp;
    __shared__ int s_ig, s_ih, s_lg, s_ll;

    // --- L2: each of 64 threads merges 64 chunk candidate lists ---
    if (tid < 2 * L2GROUPS) {
        int upper = (tid >= L2GROUPS);
        int g = upper ? tid - L2GROUPS : tid;
        const int* cand = upper ? g_candUp : g_candLo;
        const int* cnt  = upper ? g_candCntUp : g_candCntLo;
        int* out = (upper ? g_l2Up : g_l2Lo) + (size_t)g * L2STRIDE;
        int sp = 0;
        for (int c = g * CHPERGRP; c < (g + 1) * CHPERGRP; ++c) {
            int n = cnt[c];
            const int* src = cand + (size_t)c * CAP;
            for (int k = 0; k < n; ++k) {
                int idx = src[k];
                graham_push(out, sp, idx, g_xs[idx]);
            }
        }
        (upper ? g_l2CntUp : g_l2CntLo)[g] = sp;
    }
    __syncthreads();

    // --- L3: final sequential merges (two concurrent warps) ---
    if (tid == 0) {
        int sp = 0;
        for (int g = 0; g < L2GROUPS; ++g) {
            int n = g_l2CntLo[g];
            const int* src = g_l2Lo + (size_t)g * L2STRIDE;
            for (int k = 0; k < n; ++k) {
                int idx = src[k];
                graham_push(g_hullLo, sp, idx, g_xs[idx]);
            }
        }
        s_mLo = sp;
    } else if (tid == 32) {
        int sp = 0;
        for (int g = 0; g < L2GROUPS; ++g) {
            int n = g_l2CntUp[g];
            const int* src = g_l2Up + (size_t)g * L2STRIDE;
            for (int k = 0; k < n; ++k) {
                int idx = src[k];
                graham_push(g_hullUp, sp, idx, g_xs[idx]);
            }
        }
        s_mUp = sp;
    }
    __syncthreads();

    // --- chains + zigzag on thread 0 ---
    if (tid == 0) {
        const double* xs = g_xs;
        int low = g_low, high = g_high;

        // gcm: descending from high (hullLo ascending, last element == high),
        // stop at first vertex <= low  (hullLo[0] == 1 guarantees termination)
        {
            int k = s_mLo - 1, i = 1;
            while (true) {
                int v = g_hullLo[k];
                g_gcm[i] = v;
                if (v <= low) break;
                --k; ++i;
            }
            s_lg = i;
        }
        // lcm: ascending from low (hullUp descending, last element == low),
        // stop at first vertex >= high (hullUp[0] == N guarantees termination)
        {
            int k = s_mUp - 1, i = 1;
            while (true) {
                int v = g_hullUp[k];
                g_lcm[i] = v;
                if (v >= high) break;
                --k; ++i;
            }
            s_ll = i;
        }

        int l_gcm = s_lg, l_lcm = s_ll;
        int ig = l_gcm, ih = l_lcm;
        int ix = l_gcm - 1, iv = 2;
        double d = 0.0;
        if (l_gcm != 2 || l_lcm != 2) {
            while (true) {
                int gcmix = g_gcm[ix], lcmiv = g_lcm[iv];
                if (gcmix > lcmiv) {
                    int gcmi1 = g_gcm[ix + 1];
                    double t = ((double)lcmiv - (double)gcmi1 + 1.0)
                             - (xs[lcmiv] - xs[gcmi1]) * (double)(gcmix - gcmi1)
                               / (xs[gcmix] - xs[gcmi1]);
                    ++iv;
                    if (t >= d) { d = t; ig = ix + 1; ih = iv - 1; }
                } else {
                    int lcmiv1 = g_lcm[iv - 1];
                    double t = (xs[gcmix] - xs[lcmiv1]) * (double)(lcmiv - lcmiv1)
                               / (xs[lcmiv] - xs[lcmiv1])
                             - ((double)gcmix - (double)lcmiv1 - 1.0);
                    --ix;
                    if (t > d) { d = t; ig = ix + 1; ih = iv; }
                }
                if (ix < 1) ix = 1;
                if (iv > l_lcm) iv = l_lcm;
                if (g_gcm[ix] == g_lcm[iv]) break;
            }
        } else {
            d = 1.0;
        }
        s_ig = ig; s_ih = ih;
        g_ig = ig; g_ih = ih; g_lgcm = l_gcm; g_llcm = l_lcm;
        g_scanmax = 0ull;
        if (d < g_dip) g_done = 1;
    }
    __syncthreads();
    if (g_done) return;

    // --- per-segment slope C precompute (parallel) ---
    int ig = s_ig, ih = s_ih, lg = s_lg, ll = s_ll;
    for (int j = ig + tid; j < lg; j += 1024) {
        int jb = g_gcm[j + 1], je = g_gcm[j];
        double C = 0.0;
        if (je - jb > 1 && g_xs[je] != g_xs[jb])
            C = (double)(je - jb) / (g_xs[je] - g_xs[jb]);
        g_segCLo[j] = C;
    }
    for (int j = ih + tid; j < ll; j += 1024) {
        int jb = g_lcm[j], je = g_lcm[j + 1];
        double C = 0.0;
        if (je - jb > 1 && g_xs[je] != g_xs[jb])
            C = (double)(je - jb) / (g_xs[je] - g_xs[jb]);
        g_segCUp[j] = C;
    }
}

// ---------------------------------------------------------------------------
// kC: grid-wide segment max scan -> atomicMax(g_scanmax)
// ---------------------------------------------------------------------------
__global__ void scan_seg_kernel()
{
    if (g_done) return;
    int ig = g_ig, ih = g_ih, lg = g_lgcm, ll = g_llcm;

    long cntLo = 0, cntUp = 0;
    int loA = 0, upA = 0;
    if (ig < lg) { loA = g_gcm[lg]; cntLo = (long)g_gcm[ig] - loA + 1; }
    if (ih < ll) { upA = g_lcm[ih]; cntUp = (long)g_lcm[ll] - upA + 1; }
    long tot = cntLo + cntUp;

    double local = 0.0;
    long stride = (long)gridDim.x * blockDim.x;
    for (long e = (long)blockIdx.x * blockDim.x + threadIdx.x; e < tot; e += stride) {
        if (e < cntLo) {
            int i = loA + (int)e;
            // smallest j in [ig, lg-1] with gcm[j+1] <= i
            int a = ig, b = lg - 1;
            while (a < b) { int m = (a + b) >> 1; if (g_gcm[m + 1] <= i) b = m; else a = m + 1; }
            double C = g_segCLo[a];
            if (C != 0.0) {
                int jb = g_gcm[a + 1];
                double t = (double)(i - jb + 1) - (g_xs[i] - g_xs[jb]) * C;
                if (t > local) local = t;
            }
        } else {
            int i = upA + (int)(e - cntLo);
            // largest j in [ih, ll-1] with lcm[j] <= i
            int a = ih, b = ll - 1;
            while (a < b) { int m = (a + b + 1) >> 1; if (g_lcm[m] <= i) a = m; else b = m - 1; }
            double C = g_segCUp[a];
            if (C != 0.0) {
                int jb = g_lcm[a];
                double t = (g_xs[i] - g_xs[jb]) * C - (double)(i - jb - 1);
                if (t > local) local = t;
            }
        }
    }

    __shared__ double red[256];
    int t = threadIdx.x;
    red[t] = local;
    __syncthreads();
    #pragma unroll
    for (int off = 128; off >= 1; off >>= 1) {
        if (t < off) { double o = red[t + off]; if (o > red[t]) red[t] = o; }
        __syncthreads();
    }
    if (t == 0 && red[0] > 1.0)
        atomicMax(&g_scanmax, (unsigned long long)__double_as_longlong(red[0]));
}

// ---------------------------------------------------------------------------
// kD: scalar update of dip / low / high / done, write output
// ---------------------------------------------------------------------------
__global__ void update_kernel(float* out, int N)
{
    if (g_done) return;
    double dip = g_dip;
    double sm = __longlong_as_double((long long)g_scanmax);
    if (sm > dip) dip = sm;
    g_dip = dip;
    out[0] = (float)(dip / (2.0 * (double)N));
    int nlow = g_gcm[g_ig], nhigh = g_lcm[g_ih];
    if (nlow == g_low && nhigh == g_high) {
        g_done = 1;
    } else {
        g_low = nlow; g_high = nhigh;
    }
}

// ---------------------------------------------------------------------------
// kernel_launch
// ---------------------------------------------------------------------------
extern "C" void kernel_launch(void* const* d_in, const int* in_sizes, int n_in,
                              void* d_out, int out_size)
{
    const float* X   = (const float*)d_in[0];
    const float* P   = (const float*)d_in[1];
    const int*   idx = (const int*)d_in[2];
    float*       out = (float*)d_out;

    int N    = in_sizes[0] / DDIM;
    int NB   = (N + 255) / 256;
    int NPAD = NB * 256;

    // 1) projection + key transform + padding
    proj_kernel<<<(N + 7) / 8, 256>>>(X, P, idx, N, NPAD);

    // 2) radix sort, 4 passes of 8 bits (A->B->A->B->A)
    int srcIsA = 1;
    for (int pass = 0; pass < 4; ++pass) {
        int shift = pass * 8;
        hist_kernel<<<NB, 256>>>(srcIsA, shift, NB);
        scan_digit_kernel<<<256, 256>>>(NB);
        scan_base_kernel<<<1, 256>>>();
        scatter_kernel<<<NB, 256>>>(srcIsA, shift, NB);
        srcIsA ^= 1;
    }

    // 3) sorted keys -> double xs[1..N], init dip state
    finalize_kernel<<<(N + 255) / 256, 256>>>(N);
    dip_init_kernel<<<1, 1>>>(out, N);

    // 4) dip outer loop, unrolled to MAXIT device-gated iterations
    for (int it = 0; it < MAXIT; ++it) {
        hull_l1_kernel<<<(2 * CHUNKS) / 256, 256>>>(N);
        merge_kernel<<<1, 1024>>>(N);
        scan_seg_kernel<<<96, 256>>>();
        update_kernel<<<1, 1>>>(out, N);
    }
}

// round 7
// speedup vs baseline: 3.1915x; 3.1915x over previous
#include <cuda_runtime.h>
#include <cstdint>

#define DDIM    128
#define NMAXPAD 200704
#define NBMAX   784

#define CS      128
#define NCHMAX  1568
#define GSZ     32
#define NGMAX   49
#define CCAP    128
#define GCAP    4096
#define PCAP    4096
#define SCAP    1024
#define MAXIT   48
#define SCANB   96

// ---------------- static scratch (~20 MB total) ----------------
__device__ unsigned g_keysA[NMAXPAD];
__device__ unsigned g_keysB[NMAXPAD];
__device__ unsigned g_hist[256 * NBMAX];
__device__ unsigned g_prefix[256 * NBMAX];
__device__ unsigned g_digitTotal[256];
__device__ unsigned g_digitBase[256];
__device__ double   g_xs[NMAXPAD + 2];

__device__ int g_candLoI[NCHMAX * CCAP];
__device__ int g_candUpI[NCHMAX * CCAP];
__device__ int g_candCntLo[NCHMAX], g_candCntUp[NCHMAX];
__device__ int g_grpLoI[NGMAX * GCAP];
__device__ int g_grpUpI[NGMAX * GCAP];
__device__ int g_grpCntLo[NGMAX], g_grpCntUp[NGMAX];
__device__ int g_preLoI[NGMAX * PCAP];
__device__ int g_preUpI[NGMAX * PCAP];
__device__ int g_preCntLo[NGMAX], g_preCntUp[NGMAX];
__device__ int g_stkLoI[NCHMAX * SCAP];
__device__ int g_stkUpI[NCHMAX * SCAP];

__device__ int g_mn[NMAXPAD + 2];
__device__ int g_mj[NMAXPAD + 2];
__device__ int g_gcm[NMAXPAD + 2];
__device__ int g_lcm[NMAXPAD + 2];
__device__ int    g_segJbLo[NMAXPAD + 2]; __device__ double g_segXbLo[NMAXPAD + 2]; __device__ double g_segCLo[NMAXPAD + 2];
__device__ int    g_segJbUp[NMAXPAD + 2]; __device__ double g_segXbUp[NMAXPAD + 2]; __device__ double g_segCUp[NMAXPAD + 2];

__device__ int    g_low, g_high, g_done, g_count;
__device__ int    g_ig, g_ih, g_nsegLo, g_nsegUp, g_loA, g_loB, g_upA, g_upB;
__device__ double g_dip;
__device__ unsigned long long g_scanmax;

// Graham push, exact reference pop predicate; xs of top-2 carried in regs,
// reloaded from g_xs only on pops (amortized rare).
__device__ __forceinline__ void cpush(int* si, int cap, int& sp,
                                      double& xt, double& xb, int idx, double x)
{
    while (sp >= 2) {
        int tt = si[sp - 1], bb = si[sp - 2];
        if ((x - xt) * (double)(tt - bb) < (xt - xb) * (double)(idx - tt)) break;
        --sp; xt = xb; xb = (sp >= 2) ? g_xs[si[sp - 2]] : 0.0;
    }
    if (sp >= cap) sp = cap - 1;
    si[sp] = idx; ++sp;
    xb = xt; xt = x;
}

// ---------------- projection ----------------
__global__ void proj_kernel(const float* __restrict__ X, const float* __restrict__ P,
                            const int* __restrict__ idx, int N, int NPAD)
{
    int gtid = blockIdx.x * blockDim.x + threadIdx.x;
    int warpId = gtid >> 5, lane = threadIdx.x & 31;
    const float4* p4 = (const float4*)(P + (size_t)(*idx) * DDIM);
    float4 pv = p4[lane];
    if (warpId < N) {
        const float4* x4 = (const float4*)(X + (size_t)warpId * DDIM);
        float4 xv = x4[lane];
        float s = xv.x * pv.x + xv.y * pv.y + xv.z * pv.z + xv.w * pv.w;
        #pragma unroll
        for (int off = 16; off; off >>= 1) s += __shfl_xor_sync(0xffffffffu, s, off);
        if (lane == 0) {
            unsigned b = __float_as_uint(s);
            g_keysA[warpId] = (b & 0x80000000u) ? ~b : (b | 0x80000000u);
        }
    }
    if (gtid < NPAD - N) g_keysA[N + gtid] = 0xFFFFFFFFu;
}

// ---------------- radix sort (4 x 8-bit) ----------------
__global__ void hist_kernel(int srcIsA, int shift, int NB)
{
    const unsigned* in = srcIsA ? g_keysA : g_keysB;
    __shared__ unsigned sh[256];
    sh[threadIdx.x] = 0; __syncthreads();
    unsigned key = in[blockIdx.x * 256 + threadIdx.x];
    atomicAdd(&sh[(key >> shift) & 255u], 1u);
    __syncthreads();
    g_hist[threadIdx.x * NB + blockIdx.x] = sh[threadIdx.x];
}

__global__ void scan_digit_kernel(int NB)
{
    int d = blockIdx.x, t = threadIdx.x;
    __shared__ unsigned sh[256]; __shared__ unsigned s_tot;
    unsigned carry = 0;
    for (int base = 0; base < NB; base += 256) {
        int i = base + t;
        unsigned v = (i < NB) ? g_hist[d * NB + i] : 0u;
        sh[t] = v; __syncthreads();
        unsigned x = v;
        #pragma unroll
        for (int off = 1; off < 256; off <<= 1) {
            unsigned y = (t >= off) ? sh[t - off] : 0u;
            __syncthreads();
            if (t >= off) x += y;
            sh[t] = x; __syncthreads();
        }
        if (i < NB) g_prefix[d * NB + i] = carry + x - v;
        if (t == 255) s_tot = x;
        __syncthreads();
        carry += s_tot; __syncthreads();
    }
    if (t == 0) g_digitTotal[d] = carry;
}

__global__ void scan_base_kernel()
{
    int t = threadIdx.x;
    __shared__ unsigned sh[256];
    unsigned v = g_digitTotal[t];
    sh[t] = v; __syncthreads();
    unsigned x = v;
    #pragma unroll
    for (int off = 1; off < 256; off <<= 1) {
        unsigned y = (t >= off) ? sh[t - off] : 0u;
        __syncthreads();
        if (t >= off) x += y;
        sh[t] = x; __syncthreads();
    }
    g_digitBase[t] = x - v;
}

__global__ void scatter_kernel(int srcIsA, int shift, int NB)
{
    const unsigned* in  = srcIsA ? g_keysA : g_keysB;
    unsigned*       out = srcIsA ? g_keysB : g_keysA;
    __shared__ unsigned warpHist[8][256];
    int t = threadIdx.x, w = t >> 5, lane = t & 31;
    for (int i = t; i < 8 * 256; i += 256) ((unsigned*)warpHist)[i] = 0u;
    __syncthreads();
    unsigned key = in[blockIdx.x * 256 + t];
    unsigned d = (key >> shift) & 255u;
    unsigned peers = __match_any_sync(0xffffffffu, d);
    unsigned rank = __popc(peers & ((1u << lane) - 1u));
    if (lane == __ffs(peers) - 1) warpHist[w][d] = __popc(peers);
    __syncthreads();
    unsigned base = 0;
    for (int w2 = 0; w2 < w; ++w2) base += warpHist[w2][d];
    out[g_digitBase[d] + g_prefix[d * NB + blockIdx.x] + base + rank] = key;
}

__global__ void finalize_kernel(int N)
{
    int i = blockIdx.x * blockDim.x + threadIdx.x;
    if (i == 0) g_xs[0] = 0.0;
    if (i < N) {
        unsigned k = g_keysA[i];
        unsigned b = (k & 0x80000000u) ? (k ^ 0x80000000u) : ~k;
        g_xs[i + 1] = (double)__uint_as_float(b);
    }
}

__global__ void dip_init_kernel(float* out, int N)
{
    g_low = 1; g_high = N; g_dip = 1.0;
    g_done = (N < 4 || g_xs[1] == g_xs[N]) ? 1 : 0;
    out[0] = (float)(1.0 / (2.0 * (double)(N > 1 ? N : 1)));
}

// ---------------- one-time hull structure build ----------------
__global__ void chunk_kernel(int N, int NCH)
{
    int t = blockIdx.x * blockDim.x + threadIdx.x;
    if (t >= 2 * NCH) return;
    int side = t >= NCH, c = side ? t - NCH : t;   // upper: c is reversed id
    if (!side) {
        int* si = g_candLoI + (size_t)c * CCAP;
        int sp = 0; double xt = 0.0, xb = 0.0;
        int s = 1 + c * CS, e = s + CS - 1; if (e > N) e = N;
        for (int j = s; j <= e; ++j) cpush(si, CCAP, sp, xt, xb, j, g_xs[j]);
        g_candCntLo[c] = sp;
    } else {
        int cc = NCH - 1 - c;
        int* si = g_candUpI + (size_t)c * CCAP;
        int sp = 0; double xt = 0.0, xb = 0.0;
        int s = 1 + cc * CS, e = s + CS - 1; if (e > N) e = N;
        for (int k = e; k >= s; --k) cpush(si, CCAP, sp, xt, xb, k, g_xs[k]);
        g_candCntUp[c] = sp;
    }
}

__global__ void group_kernel(int N, int NCH, int NG)
{
    int b = blockIdx.x;
    if (threadIdx.x != 0 || b >= 2 * NG) return;
    int side = b >= NG, g = side ? b - NG : b;
    const int* ci = side ? g_candUpI : g_candLoI;
    const int* cn = side ? g_candCntUp : g_candCntLo;
    int* si = (side ? g_grpUpI : g_grpLoI) + (size_t)g * GCAP;
    int sp = 0; double xt = 0.0, xb = 0.0;
    int c0 = g * GSZ, c1 = c0 + GSZ; if (c1 > NCH) c1 = NCH;
    for (int c = c0; c < c1; ++c) {
        int n = cn[c]; if (n > CCAP) n = CCAP;
        const int* li = ci + (size_t)c * CCAP;
        for (int k = 0; k < n; ++k) { int idx = li[k]; cpush(si, GCAP, sp, xt, xb, idx, g_xs[idx]); }
    }
    (side ? g_grpCntUp : g_grpCntLo)[g] = sp;
}

__global__ void prefixg_kernel(int NG)
{
    int b = blockIdx.x;
    if (threadIdx.x != 0 || b >= 2 * NG) return;
    int side = b >= NG, g = side ? b - NG : b;
    const int* gi = side ? g_grpUpI : g_grpLoI;
    const int* gn = side ? g_grpCntUp : g_grpCntLo;
    int* si = (side ? g_preUpI : g_preLoI) + (size_t)g * PCAP;
    int sp = 0; double xt = 0.0, xb = 0.0;
    for (int gg = 0; gg < g; ++gg) {
        int n = gn[gg]; if (n > GCAP) n = GCAP;
        const int* li = gi + (size_t)gg * GCAP;
        for (int k = 0; k < n; ++k) { int idx = li[k]; cpush(si, PCAP, sp, xt, xb, idx, g_xs[idx]); }
    }
    (side ? g_preCntUp : g_preCntLo)[g] = sp;
}

// per-chunk completion: exact mn[] / mj[] for every index
__global__ void mncomp_kernel(int N, int NCH)
{
    int t = blockIdx.x * blockDim.x + threadIdx.x;
    if (t >= 2 * NCH) return;
    int side = t >= NCH, c = side ? t - NCH : t;
    int g = c / GSZ;
    if (!side) {
        int* si = g_stkLoI + (size_t)c * SCAP;
        int sp = g_preCntLo[g]; if (sp > SCAP) sp = SCAP;
        const int* pi = g_preLoI + (size_t)g * PCAP;
        for (int k = 0; k < sp; ++k) si[k] = pi[k];
        double xt = sp ? g_xs[si[sp - 1]] : 0.0, xb = sp >= 2 ? g_xs[si[sp - 2]] : 0.0;
        for (int cc = g * GSZ; cc < c; ++cc) {
            int n = g_candCntLo[cc]; if (n > CCAP) n = CCAP;
            const int* li = g_candLoI + (size_t)cc * CCAP;
            for (int k = 0; k < n; ++k) { int idx = li[k]; cpush(si, SCAP, sp, xt, xb, idx, g_xs[idx]); }
        }
        int s = 1 + c * CS, e = s + CS - 1; if (e > N) e = N;
        for (int j = s; j <= e; ++j) {
            double x = g_xs[j];
            while (sp >= 2) {
                int tt = si[sp - 1], bb = si[sp - 2];
                if ((x - xt) * (double)(tt - bb) < (xt - xb) * (double)(j - tt)) break;
                --sp; xt = xb; xb = (sp >= 2) ? g_xs[si[sp - 2]] : 0.0;
            }
            g_mn[j] = sp ? si[sp - 1] : j;
            if (sp >= SCAP) sp = SCAP - 1;
            si[sp] = j; ++sp; xb = xt; xt = x;
        }
    } else {
        int cc = NCH - 1 - c;
        int* si = g_stkUpI + (size_t)c * SCAP;
        int sp = g_preCntUp[g]; if (sp > SCAP) sp = SCAP;
        const int* pi = g_preUpI + (size_t)g * PCAP;
        for (int k = 0; k < sp; ++k) si[k] = pi[k];
        double xt = sp ? g_xs[si[sp - 1]] : 0.0, xb = sp >= 2 ? g_xs[si[sp - 2]] : 0.0;
        for (int rr = g * GSZ; rr < c; ++rr) {
            int n = g_candCntUp[rr]; if (n > CCAP) n = CCAP;
            const int* li = g_candUpI + (size_t)rr * CCAP;
            for (int k = 0; k < n; ++k) { int idx = li[k]; cpush(si, SCAP, sp, xt, xb, idx, g_xs[idx]); }
        }
        int s = 1 + cc * CS, e = s + CS - 1; if (e > N) e = N;
        for (int k = e; k >= s; --k) {
            double x = g_xs[k];
            while (sp >= 2) {
                int tt = si[sp - 1], bb = si[sp - 2];
                if ((x - xt) * (double)(tt - bb) < (xt - xb) * (double)(k - tt)) break;
                --sp; xt = xb; xb = (sp >= 2) ? g_xs[si[sp - 2]] : 0.0;
            }
            g_mj[k] = sp ? si[sp - 1] : k;
            if (sp >= SCAP) sp = SCAP - 1;
            si[sp] = k; ++sp; xb = xt; xt = x;
        }
    }
}

// ---------------- per-iteration: chains + zigzag + segment setup ----------------
__global__ void __launch_bounds__(128, 1) iterA_kernel(int N)
{
    if (g_done) return;
    int tid = threadIdx.x;
    __shared__ int s_ig, s_ih, s_lg, s_ll;
    if (tid == 0) {
        const double* xs = g_xs;
        int low = g_low, high = g_high;
        int bad = 0;

        // gcm chain (bounded pointer-chase; mn[j] < j for j>1 guarantees progress)
        g_gcm[1] = high;
        int i = 1;
        while (g_gcm[i] > low && i < NMAXPAD) {
            int nxt = g_mn[g_gcm[i]];
            if (nxt >= g_gcm[i]) { bad = 1; break; }   // malformed: bail, never hang
            g_gcm[i + 1] = nxt; ++i;
        }
        int l_gcm = i;

        // lcm chain
        g_lcm[1] = low;
        i = 1;
        while (g_lcm[i] < high && i < NMAXPAD) {
            int nxt = g_mj[g_lcm[i]];
            if (nxt <= g_lcm[i]) { bad = 1; break; }
            g_lcm[i + 1] = nxt; ++i;
        }
        int l_lcm = i;

        int ig = l_gcm, ih = l_lcm, ix = l_gcm - 1, iv = 2;
        double d = 0.0;
        if (!bad && (l_gcm != 2 || l_lcm != 2)) {
            int guard = 4 * (l_gcm + l_lcm) + 64;      // zigzag advances ix or iv each step
            while (guard-- > 0) {
                int gcmix = g_gcm[ix], lcmiv = g_lcm[iv];
                if (gcmix > lcmiv) {
                    int gcmi1 = g_gcm[ix + 1];
                    double tv = ((double)lcmiv - (double)gcmi1 + 1.0)
                              - (xs[lcmiv] - xs[gcmi1]) * (double)(gcmix - gcmi1) / (xs[gcmix] - xs[gcmi1]);
                    ++iv;
                    if (tv >= d) { d = tv; ig = ix + 1; ih = iv - 1; }
                } else {
                    int lcmiv1 = g_lcm[iv - 1];
                    double tv = (xs[gcmix] - xs[lcmiv1]) * (double)(lcmiv - lcmiv1) / (xs[lcmiv] - xs[lcmiv1])
                              - ((double)gcmix - (double)lcmiv1 - 1.0);
                    --ix;
                    if (tv > d) { d = tv; ig = ix + 1; ih = iv; }
                }
                if (ix < 1) ix = 1;
                if (iv > l_lcm) iv = l_lcm;
                if (g_gcm[ix] == g_lcm[iv]) break;
            }
            if (guard <= 0) bad = 1;
        } else if (!bad) {
            d = 1.0;
        }

        s_ig = ig; s_ih = ih; s_lg = l_gcm; s_ll = l_lcm;
        g_ig = ig; g_ih = ih;
        g_nsegLo = l_gcm - ig; g_nsegUp = l_lcm - ih;
        g_loA = g_gcm[l_gcm]; g_loB = g_gcm[ig];
        g_upA = g_lcm[ih];    g_upB = g_lcm[l_lcm];
        g_scanmax = 0ull; g_count = 0;
        if (bad || d < g_dip) g_done = 1;
    }
    __syncthreads();
    if (g_done) return;
    int ig = s_ig, ih = s_ih, lg = s_lg, ll = s_ll;
    for (int s = tid; s < lg - ig; s += 128) {
        int j = lg - 1 - s;                 // segments ascending in index
        int jb = g_gcm[j + 1], je = g_gcm[j];
        double C = 0.0;
        if (je - jb > 1 && g_xs[je] != g_xs[jb]) C = (double)(je - jb) / (g_xs[je] - g_xs[jb]);
        g_segJbLo[s] = jb; g_segXbLo[s] = g_xs[jb]; g_segCLo[s] = C;
    }
    for (int s = tid; s < ll - ih; s += 128) {
        int j = ih + s;
        int jb = g_lcm[j], je = g_lcm[j + 1];
        double C = 0.0;
        if (je - jb > 1 && g_xs[je] != g_xs[jb]) C = (double)(je - jb) / (g_xs[je] - g_xs[jb]);
        g_segJbUp[s] = jb; g_segXbUp[s] = g_xs[jb]; g_segCUp[s] = C;
    }
}

// ---------------- per-iteration: wide segment-max scan + state update ----------------
__global__ void scanB_kernel(float* out, int N)
{
    if (g_done) return;
    int nLo = g_nsegLo, nUp = g_nsegUp;
    int loA = g_loA, upA = g_upA;
    long cntLo = nLo > 0 ? (long)g_loB - loA + 1 : 0;
    long cntUp = nUp > 0 ? (long)g_upB - upA + 1 : 0;
    if (cntLo < 0) cntLo = 0;
    if (cntUp < 0) cntUp = 0;
    long tot = cntLo + cntUp;

    double local = 0.0;
    long stride = (long)gridDim.x * blockDim.x;
    for (long e = (long)blockIdx.x * blockDim.x + threadIdx.x; e < tot; e += stride) {
        if (e < cntLo) {
            int i = loA + (int)e;
            int a = 0, b = nLo - 1;
            while (a < b) { int m = (a + b + 1) >> 1; if (g_segJbLo[m] <= i) a = m; else b = m - 1; }
            double C = g_segCLo[a];
            if (C != 0.0) {
                double tv = (double)(i - g_segJbLo[a] + 1) - (g_xs[i] - g_segXbLo[a]) * C;
                if (tv > local) local = tv;
            }
        } else {
            int i = upA + (int)(e - cntLo);
            int a = 0, b = nUp - 1;
            while (a < b) { int m = (a + b + 1) >> 1; if (g_segJbUp[m] <= i) a = m; else b = m - 1; }
            double C = g_segCUp[a];
            if (C != 0.0) {
                double tv = (g_xs[i] - g_segXbUp[a]) * C - (double)(i - g_segJbUp[a] - 1);
                if (tv > local) local = tv;
            }
        }
    }

    __shared__ double red[256];
    int t = threadIdx.x;
    red[t] = local; __syncthreads();
    #pragma unroll
    for (int off = 128; off >= 1; off >>= 1) {
        if (t < off) { double o = red[t + off]; if (o > red[t]) red[t] = o; }
        __syncthreads();
    }
    if (t == 0) {
        if (red[0] > 1.0)
            atomicMax(&g_scanmax, (unsigned long long)__double_as_longlong(red[0]));
        __threadfence();
        int old = atomicAdd(&g_count, 1);
        if (old == gridDim.x - 1) {   // last arriving block does the scalar update
            double dip = g_dip;
            double sm = __longlong_as_double((long long)g_scanmax);
            if (sm > dip) dip = sm;
            g_dip = dip;
            out[0] = (float)(dip / (2.0 * (double)N));
            int nlow = g_gcm[g_ig], nhigh = g_lcm[g_ih];
            if (nlow == g_low && nhigh == g_high) g_done = 1;
            else { g_low = nlow; g_high = nhigh; }
        }
    }
}

// ---------------- launch ----------------
extern "C" void kernel_launch(void* const* d_in, const int* in_sizes, int n_in,
                              void* d_out, int out_size)
{
    const float* X = (const float*)d_in[0];
    const float* P = (const float*)d_in[1];
    const int* idx = (const int*)d_in[2];
    float* out = (float*)d_out;

    int N = in_sizes[0] / DDIM;
    int NB = (N + 255) / 256;
    int NPAD = NB * 256;
    int NCH = (N + CS - 1) / CS;
    int NG  = (NCH + GSZ - 1) / GSZ;

    proj_kernel<<<(N + 7) / 8, 256>>>(X, P, idx, N, NPAD);

    int srcIsA = 1;
    for (int pass = 0; pass < 4; ++pass) {
        int shift = pass * 8;
        hist_kernel<<<NB, 256>>>(srcIsA, shift, NB);
        scan_digit_kernel<<<256, 256>>>(NB);
        scan_base_kernel<<<1, 256>>>();
        scatter_kernel<<<NB, 256>>>(srcIsA, shift, NB);
        srcIsA ^= 1;
    }

    finalize_kernel<<<(N + 255) / 256, 256>>>(N);
    dip_init_kernel<<<1, 1>>>(out, N);

    // one-time exact mn[] / mj[] build (reference computes these once, too)
    chunk_kernel<<<(2 * NCH + 255) / 256, 256>>>(N, NCH);
    group_kernel<<<2 * NG, 32>>>(N, NCH, NG);
    prefixg_kernel<<<2 * NG, 32>>>(NG);
    mncomp_kernel<<<(2 * NCH + 255) / 256, 256>>>(N, NCH);

    // Hartigan loop: 2 kernels per (device-gated) iteration
    for (int it = 0; it < MAXIT; ++it) {
        iterA_kernel<<<1, 128>>>(N);
        scanB_kernel<<<SCANB, 256>>>(out, N);
    }
}